// round 13
// baseline (speedup 1.0000x reference)
#include <cuda_runtime.h>
#include <cuda_fp16.h>
#include <cstdint>

#define DINLINE __device__ __forceinline__

// ============================================================================
// KAN layer as one fp16 tensor-core GEMM (mma.sync m16n8k16 HMMA path).
// R11 baseline: 602.9 us, rel_err 2.86e-4. gen_A=66.6us, gen_W~10us,
// GEMM ~520us = 2.4x above tensor-issue floor => latency-stalled mainloop
// (ldsm->mma short-scoreboard exposed each kk, only 2 warps/SMSP).
// R12 change: fragment double-buffering across kk (ping-pong a/b register
// sets) so kk+1's LDSM fly under kk's 32-HMMA drain. ~217 regs, no spill
// expected; fallback if spilling: B-only dbuf (-32 regs).
// ============================================================================

// ---------------- problem constants ----------------
constexpr int BATCH = 8192;
constexpr int INF   = 1024;
constexpr int OUTF  = 1024;
constexpr int K12   = 12;              // 11 spline bases + 1 silu/base slot
constexpr int KDIM  = INF * K12;       // 12288
constexpr float WSCALE     = 1024.0f;
constexpr float INV_WSCALE = 1.0f / 1024.0f;

// ---------------- GEMM tiling ----------------
constexpr int TM = 128;                // CTA M tile
constexpr int TN = 256;                // CTA N tile
constexpr int TK = 64;                 // K per stage (64 fp16 = 128B row, SW128 native)
constexpr int STAGES = 4;
constexpr int A_TILE_B = TM * TK * 2;  // 16 KB
constexpr int W_TILE_B = TN * TK * 2;  // 32 KB
constexpr int STAGE_B  = A_TILE_B + W_TILE_B;  // 48 KB
constexpr int SMEM_DYN = STAGES * STAGE_B + 1024;  // 193 KB (+align slack)
constexpr int NKI = KDIM / TK;         // 192 K iterations
constexpr int NTHREADS = 256;          // 8 warps: 2 (M) x 4 (N), warp tile 64x64

// ---------------- scratch (static device globals; no allocs) ----------------
__device__ __align__(128) __half g_A[(size_t)BATCH * KDIM];   // 201 MB fp16 activations
__device__ __align__(128) __half g_W[(size_t)OUTF  * KDIM];   // 24 MB fp16 weights (x1024)

// ---------------- helpers ----------------
DINLINE uint32_t smem_u32(const void* p) {
    uint32_t a;
    asm("{ .reg .u64 t; cvta.to.shared.u64 t, %1; cvt.u32.u64 %0, t; }" : "=r"(a) : "l"(p));
    return a;
}
DINLINE void cp_async16(uint32_t saddr, const void* gptr) {
    asm volatile("cp.async.cg.shared.global [%0], [%1], 16;" :: "r"(saddr), "l"(gptr));
}
#define CP_COMMIT() asm volatile("cp.async.commit_group;" ::: "memory")
#define CP_WAIT2()  asm volatile("cp.async.wait_group 2;"  ::: "memory")

DINLINE uint32_t sw128(uint32_t off) { return off ^ ((off >> 3) & 0x70); }

DINLINE void ldsm_x4(uint32_t* r, uint32_t addr) {
    asm volatile("ldmatrix.sync.aligned.m8n8.x4.shared.b16 {%0,%1,%2,%3}, [%4];"
                 : "=r"(r[0]), "=r"(r[1]), "=r"(r[2]), "=r"(r[3]) : "r"(addr));
}
DINLINE void mma16816(float* c, const uint32_t* a, uint32_t b0, uint32_t b1) {
    asm volatile(
        "mma.sync.aligned.m16n8k16.row.col.f32.f16.f16.f32 "
        "{%0,%1,%2,%3}, {%4,%5,%6,%7}, {%8,%9}, {%0,%1,%2,%3};"
        : "+f"(c[0]), "+f"(c[1]), "+f"(c[2]), "+f"(c[3])
        : "r"(a[0]), "r"(a[1]), "r"(a[2]), "r"(a[3]), "r"(b0), "r"(b1));
}

// ---------------- packing math shared by prep kernels ----------------
DINLINE void pack12_from_x(float xv, uint32_t* words) {
    __half vals[12];
#pragma unroll
    for (int j = 0; j < 11; j++) {
        float c = -1.25f + 0.25f * (float)j;
        float u = fabsf(xv - c) * 4.0f;                // /GRID_STEP
        float c2 = 2.0f - u, c1 = 1.0f - u;
        float v;
        if (u < 1.0f)      v = (1.0f / 6.0f) * (c2 * c2 * c2 - 4.0f * c1 * c1 * c1);
        else if (u < 2.0f) v = (1.0f / 6.0f) * (c2 * c2 * c2);
        else               v = 0.0f;
        vals[j] = __float2half_rn(v);
    }
    vals[11] = __float2half_rn(xv / (1.0f + __expf(-xv)));   // silu
    const uint32_t* src = reinterpret_cast<const uint32_t*>(vals);
#pragma unroll
    for (int t = 0; t < 6; t++) words[t] = src[t];
}

// ---------------- prep kernel: activations -> fp16 packed A ----------------
__global__ void __launch_bounds__(256) gen_A_kernel(const float* __restrict__ x) {
    __shared__ uint32_t stage[256 * 6];                // 6 KB
    int base = blockIdx.x * 256;                       // BATCH*INF % 256 == 0
    float xv = x[base + threadIdx.x];
    uint32_t w[6];
    pack12_from_x(xv, w);
#pragma unroll
    for (int t = 0; t < 6; t++) stage[threadIdx.x * 6 + t] = w[t];
    __syncthreads();
    uint4* dst = reinterpret_cast<uint4*>(g_A + (size_t)base * K12);
    const uint4* src = reinterpret_cast<const uint4*>(stage);
#pragma unroll
    for (int i = threadIdx.x; i < 256 * 6 / 4; i += 256) dst[i] = src[i];
}

// ---------------- prep kernel: weights -> fp16 packed W (x1024) ----------------
__global__ void __launch_bounds__(256) gen_W_kernel(const float* __restrict__ bw,
                                                    const float* __restrict__ sw) {
    __shared__ uint32_t stage[256 * 6];
    int base = blockIdx.x * 256;                       // OUTF*INF % 256 == 0
    int idx = base + threadIdx.x;
    const float* sp = sw + (size_t)idx * 11;           // strided reads absorbed by L1
    __half vals[12];
#pragma unroll
    for (int j = 0; j < 11; j++) vals[j] = __float2half_rn(sp[j] * WSCALE);
    vals[11] = __float2half_rn(bw[idx] * WSCALE);
    const uint32_t* src32 = reinterpret_cast<const uint32_t*>(vals);
#pragma unroll
    for (int t = 0; t < 6; t++) stage[threadIdx.x * 6 + t] = src32[t];
    __syncthreads();
    uint4* dst = reinterpret_cast<uint4*>(g_W + (size_t)base * K12);
    const uint4* src = reinterpret_cast<const uint4*>(stage);
#pragma unroll
    for (int i = threadIdx.x; i < 256 * 6 / 4; i += 256) dst[i] = src[i];
}

// ---------------- GEMM stage loader ----------------
DINLINE void load_stage(uint32_t tiles, int slot, int blk, int tid,
                        const __half* Ag, const __half* Wg) {
    uint32_t a_s = tiles + slot * STAGE_B;
    uint32_t w_s = a_s + A_TILE_B;
    int k0 = blk * TK;
#pragma unroll
    for (int i = tid; i < TM * 8; i += NTHREADS) {
        int r = i >> 3, c = i & 7;
        uint32_t off = (uint32_t)(r * 128 + c * 16);
        cp_async16(a_s + sw128(off), Ag + (size_t)r * KDIM + k0 + c * 8);
    }
#pragma unroll
    for (int i = tid; i < TN * 8; i += NTHREADS) {
        int r = i >> 3, c = i & 7;
        uint32_t off = (uint32_t)(r * 128 + c * 16);
        cp_async16(w_s + sw128(off), Wg + (size_t)r * KDIM + k0 + c * 8);
    }
}

// ---------------- main GEMM kernel (mma.sync m16n8k16, dbuf frags) ----------
__global__ void __launch_bounds__(NTHREADS, 1) kan_gemm_kernel(float* __restrict__ out) {
    extern __shared__ char smem[];
    uint32_t sbase = smem_u32(smem);
    uint32_t tiles = (sbase + 1023u) & ~1023u;        // 1024B-aligned tile region
    int tid = threadIdx.x, lane = tid & 31, wid = tid >> 5;
    int warp_m = wid & 1;                              // 0..1 -> 64-row slice
    int warp_n = wid >> 1;                             // 0..3 -> 64-col slice
    int m0 = blockIdx.y * TM;
    int n0 = blockIdx.x * TN;

    const __half* Ag = g_A + (size_t)m0 * KDIM;
    const __half* Wg = g_W + (size_t)n0 * KDIM;

    float c[4][8][4];                                  // 128 acc regs
#pragma unroll
    for (int i = 0; i < 4; i++)
#pragma unroll
        for (int j = 0; j < 8; j++)
#pragma unroll
            for (int q = 0; q < 4; q++) c[i][j][q] = 0.0f;

    // per-thread ldmatrix row/col offsets (within warp tile)
    int a_row = (lane & 15);                           // +mt*16
    int a_colg = (lane >> 4) * 8;                      // k sub-block
    int b_row = (lane & 7) + ((lane >> 4) & 1) * 8;    // +nt2*16
    int b_colg = ((lane >> 3) & 1) * 8;                // k sub-block

    // precomputed swizzled in-tile offsets for this thread
    uint32_t a_off_base = (uint32_t)((warp_m * 64 + a_row) * 128 + a_colg * 2);
    uint32_t b_off_base = (uint32_t)((warp_n * 64 + b_row) * 128 + b_colg * 2);

    // prologue: stages 0..2
#pragma unroll
    for (int s = 0; s < STAGES - 1; s++) { load_stage(tiles, s, s, tid, Ag, Wg); CP_COMMIT(); }

    uint32_t abuf[2][4][4], bbuf[2][4][4];             // ping-pong fragment sets

    for (int t = 0; t < NKI; t++) {
        CP_WAIT2();                                    // stage t landed (<=2 groups pending)
        __syncthreads();                               // all warps done reading slot (t-1)&3

        // refill issue BEFORE compute (slot (t+3)&3 == (t-1)&3 free now)
        int nb = t + STAGES - 1;
        if (nb < NKI) load_stage(tiles, nb & 3, nb, tid, Ag, Wg);
        CP_COMMIT();                                   // uniform group accounting

        uint32_t a_s = tiles + (t & 3) * STAGE_B;
        uint32_t w_s = a_s + A_TILE_B;

        // preload kk=0 fragments into buffer 0
#pragma unroll
        for (int mt = 0; mt < 4; mt++)
            ldsm_x4(abuf[0][mt], a_s + sw128(a_off_base + (uint32_t)(mt * 16 * 128)));
#pragma unroll
        for (int nt2 = 0; nt2 < 4; nt2++)
            ldsm_x4(bbuf[0][nt2], w_s + sw128(b_off_base + (uint32_t)(nt2 * 16 * 128)));

#pragma unroll
        for (int kk = 0; kk < 4; kk++) {               // 4 x K16 within TK=64
            int cur = kk & 1, nxt = cur ^ 1;
            if (kk < 3) {                              // prefetch kk+1 under kk's MMAs
                uint32_t koff = (uint32_t)((kk + 1) * 16 * 2);
#pragma unroll
                for (int mt = 0; mt < 4; mt++)
                    ldsm_x4(abuf[nxt][mt],
                            a_s + sw128(a_off_base + (uint32_t)(mt * 16 * 128) + koff));
#pragma unroll
                for (int nt2 = 0; nt2 < 4; nt2++)
                    ldsm_x4(bbuf[nxt][nt2],
                            w_s + sw128(b_off_base + (uint32_t)(nt2 * 16 * 128) + koff));
            }
#pragma unroll
            for (int mt = 0; mt < 4; mt++)
#pragma unroll
                for (int nt2 = 0; nt2 < 4; nt2++) {
                    mma16816(c[mt][nt2 * 2],     abuf[cur][mt], bbuf[cur][nt2][0], bbuf[cur][nt2][1]);
                    mma16816(c[mt][nt2 * 2 + 1], abuf[cur][mt], bbuf[cur][nt2][2], bbuf[cur][nt2][3]);
                }
        }
    }

    // epilogue: scale, clip, store (float2 per fragment half)
    int gr = lane >> 2, gc = (lane & 3) * 2;
#pragma unroll
    for (int mt = 0; mt < 4; mt++) {
#pragma unroll
        for (int nt = 0; nt < 8; nt++) {
            int row = m0 + warp_m * 64 + mt * 16 + gr;
            int col = n0 + warp_n * 64 + nt * 8 + gc;
            float2 v0, v1;
            v0.x = fminf(fmaxf(c[mt][nt][0] * INV_WSCALE, -1.0f), 1.0f);
            v0.y = fminf(fmaxf(c[mt][nt][1] * INV_WSCALE, -1.0f), 1.0f);
            v1.x = fminf(fmaxf(c[mt][nt][2] * INV_WSCALE, -1.0f), 1.0f);
            v1.y = fminf(fmaxf(c[mt][nt][3] * INV_WSCALE, -1.0f), 1.0f);
            *reinterpret_cast<float2*>(out + (size_t)row * OUTF + col) = v0;
            *reinterpret_cast<float2*>(out + (size_t)(row + 8) * OUTF + col) = v1;
        }
    }
}

// ---------------- launch ----------------
extern "C" void kernel_launch(void* const* d_in, const int* in_sizes, int n_in,
                              void* d_out, int out_size) {
    const float* x  = (const float*)d_in[0];   // [8192, 1024]
    const float* bw = (const float*)d_in[1];   // [1024, 1024]
    const float* sw = (const float*)d_in[2];   // [1024, 1024, 11]
    float* out = (float*)d_out;                // [8192, 1024]

    gen_A_kernel<<<BATCH * INF / 256, 256>>>(x);
    gen_W_kernel<<<OUTF * INF / 256, 256>>>(bw, sw);

    cudaFuncSetAttribute(kan_gemm_kernel,
                         cudaFuncAttributeMaxDynamicSharedMemorySize, SMEM_DYN);
    dim3 grid(OUTF / TN, BATCH / TM);          // (4, 64) = 256 CTAs
    kan_gemm_kernel<<<grid, NTHREADS, SMEM_DYN>>>(out);
}

// round 16
// speedup vs baseline: 1.0429x; 1.0429x over previous
#include <cuda_runtime.h>
#include <cuda_fp16.h>
#include <cstdint>

#define DINLINE __device__ __forceinline__

// ============================================================================
// KAN layer as one fp16 tensor-core GEMM (mma.sync m16n8k16 HMMA path).
// R11: 602.9us baseline. R13 (frag dbuf): 603.1us => NO-OP; latency
// hypothesis falsified, GEMM (~520us) pinned near legacy-HMMA issue floor.
// R14/R15/R16: attack measured issue-bound gen_A (67us, issue=71%):
//  - uniform-B-spline identity: only 4 nonzero bases, w0..w3 from f=frac(4x+5)
//    (~12 FLOPs vs ~99), scattered via SMEM dynamic stores.
//  - merge gen_A+gen_W into one launch (also shifts ncu's -s5-c1 window onto
//    the GEMM: 2 launches/replay puts launch #6 on kan_gemm_kernel).
// R15 fix: zero-fill and scatter through the SAME __half* view (aliasing).
// GEMM kept identical.
// ============================================================================

// ---------------- problem constants ----------------
constexpr int BATCH = 8192;
constexpr int INF   = 1024;
constexpr int OUTF  = 1024;
constexpr int K12   = 12;              // 11 spline bases + 1 silu/base slot
constexpr int KDIM  = INF * K12;       // 12288
constexpr float WSCALE     = 1024.0f;
constexpr float INV_WSCALE = 1.0f / 1024.0f;

// ---------------- GEMM tiling ----------------
constexpr int TM = 128;
constexpr int TN = 256;
constexpr int TK = 64;
constexpr int STAGES = 4;
constexpr int A_TILE_B = TM * TK * 2;  // 16 KB
constexpr int W_TILE_B = TN * TK * 2;  // 32 KB
constexpr int STAGE_B  = A_TILE_B + W_TILE_B;  // 48 KB
constexpr int SMEM_DYN = STAGES * STAGE_B + 1024;
constexpr int NKI = KDIM / TK;         // 192
constexpr int NTHREADS = 256;          // 8 warps: 2(M) x 4(N), warp tile 64x64

// prep kernel split
constexpr int W_BLOCKS = OUTF * INF / 256;    // 4096
constexpr int A_BLOCKS = BATCH * INF / 256;   // 32768

// ---------------- scratch (static device globals; no allocs) ----------------
__device__ __align__(128) __half g_A[(size_t)BATCH * KDIM];   // 201 MB
__device__ __align__(128) __half g_W[(size_t)OUTF  * KDIM];   // 24 MB

// ---------------- helpers ----------------
DINLINE uint32_t smem_u32(const void* p) {
    uint32_t a;
    asm("{ .reg .u64 t; cvta.to.shared.u64 t, %1; cvt.u32.u64 %0, t; }" : "=r"(a) : "l"(p));
    return a;
}
DINLINE void cp_async16(uint32_t saddr, const void* gptr) {
    asm volatile("cp.async.cg.shared.global [%0], [%1], 16;" :: "r"(saddr), "l"(gptr));
}
#define CP_COMMIT() asm volatile("cp.async.commit_group;" ::: "memory")
#define CP_WAIT2()  asm volatile("cp.async.wait_group 2;"  ::: "memory")

DINLINE uint32_t sw128(uint32_t off) { return off ^ ((off >> 3) & 0x70); }

DINLINE void ldsm_x4(uint32_t* r, uint32_t addr) {
    asm volatile("ldmatrix.sync.aligned.m8n8.x4.shared.b16 {%0,%1,%2,%3}, [%4];"
                 : "=r"(r[0]), "=r"(r[1]), "=r"(r[2]), "=r"(r[3]) : "r"(addr));
}
DINLINE void mma16816(float* c, const uint32_t* a, uint32_t b0, uint32_t b1) {
    asm volatile(
        "mma.sync.aligned.m16n8k16.row.col.f32.f16.f16.f32 "
        "{%0,%1,%2,%3}, {%4,%5,%6,%7}, {%8,%9}, {%0,%1,%2,%3};"
        : "+f"(c[0]), "+f"(c[1]), "+f"(c[2]), "+f"(c[3])
        : "r"(a[0]), "r"(a[1]), "r"(a[2]), "r"(a[3]), "r"(b0), "r"(b1));
}

// ---------------- merged prep kernel: A (windowed bspline) + W ------------
// A path: u_j = |t4 - j| with t4 = 4x+5 in [1,9]; only j = i-1..i+2 nonzero
// (i = floor(t4), f = t4 - i):
//   w0=(1-f)^3/6            (u=1+f, outer)
//   w1=((2-f)^3-4(1-f)^3)/6 (u=f,   inner)
//   w2=((1+f)^3-4f^3)/6     (u=1-f, inner; f=0 -> 1/6 = outer(u=1), continuous)
//   w3=f^3/6                (u=2-f, outer; f=0 -> 0, consistent)
__global__ void __launch_bounds__(256) gen_AW_kernel(const float* __restrict__ x,
                                                     const float* __restrict__ bw,
                                                     const float* __restrict__ sw) {
    __shared__ __align__(16) __half hstage[256 * 12];  // 6 KB
    int bid = blockIdx.x, tid = threadIdx.x;

    if (bid < W_BLOCKS) {
        // ---- W pack (x1024) ----
        int base = bid * 256;
        int idx = base + tid;
        const float* sp = sw + (size_t)idx * 11;
        __half* hp = hstage + tid * 12;
#pragma unroll
        for (int j = 0; j < 11; j++) hp[j] = __float2half_rn(sp[j] * WSCALE);
        hp[11] = __float2half_rn(bw[idx] * WSCALE);
        __syncthreads();                                 // barrier before type switch
        uint4* dst = reinterpret_cast<uint4*>(g_W + (size_t)base * K12);
        const uint4* src = reinterpret_cast<const uint4*>(hstage);
#pragma unroll
        for (int k = tid; k < 384; k += 256) dst[k] = src[k];
    } else {
        // ---- A pack (windowed B-spline + silu) ----
        int base = (bid - W_BLOCKS) * 256;
        float xv = x[base + tid];
        __half* hp = hstage + tid * 12;
        const __half hz = __float2half_rn(0.0f);
#pragma unroll
        for (int t = 0; t < 12; t++) hp[t] = hz;         // same-type zero fill

        float t4 = fmaf(xv, 4.0f, 5.0f);                 // in [1, 9]
        float fi = floorf(t4);
        int   i  = (int)fi;                              // 1..9
        float f  = t4 - fi;                              // [0,1)
        float omf = 1.0f - f, opf = 1.0f + f, tmf = 2.0f - f;
        float f3 = f * f * f, omf3 = omf * omf * omf;
        const float S = 1.0f / 6.0f;
        float w0 = S * omf3;
        float w1 = S * (tmf * tmf * tmf - 4.0f * omf3);
        float w2 = S * (opf * opf * opf - 4.0f * f3);
        float w3 = S * f3;

        hp[i - 1] = __float2half_rn(w0);                 // i>=1 -> j>=0
        hp[i]     = __float2half_rn(w1);
        hp[i + 1] = __float2half_rn(w2);                 // i<=9 -> j<=10
        if (i + 2 <= 10) hp[i + 2] = __float2half_rn(w3);
        hp[11] = __float2half_rn(xv / (1.0f + __expf(-xv)));  // silu
        __syncthreads();                                 // barrier before type switch
        uint4* dst = reinterpret_cast<uint4*>(g_A + (size_t)base * K12);
        const uint4* src = reinterpret_cast<const uint4*>(hstage);
#pragma unroll
        for (int k = tid; k < 384; k += 256) dst[k] = src[k];
    }
}

// ---------------- GEMM stage loader ----------------
DINLINE void load_stage(uint32_t tiles, int slot, int blk, int tid,
                        const __half* Ag, const __half* Wg) {
    uint32_t a_s = tiles + slot * STAGE_B;
    uint32_t w_s = a_s + A_TILE_B;
    int k0 = blk * TK;
#pragma unroll
    for (int i = tid; i < TM * 8; i += NTHREADS) {
        int r = i >> 3, c = i & 7;
        uint32_t off = (uint32_t)(r * 128 + c * 16);
        cp_async16(a_s + sw128(off), Ag + (size_t)r * KDIM + k0 + c * 8);
    }
#pragma unroll
    for (int i = tid; i < TN * 8; i += NTHREADS) {
        int r = i >> 3, c = i & 7;
        uint32_t off = (uint32_t)(r * 128 + c * 16);
        cp_async16(w_s + sw128(off), Wg + (size_t)r * KDIM + k0 + c * 8);
    }
}

// ---------------- main GEMM kernel (unchanged) ----------------
__global__ void __launch_bounds__(NTHREADS, 1) kan_gemm_kernel(float* __restrict__ out) {
    extern __shared__ char smem[];
    uint32_t sbase = smem_u32(smem);
    uint32_t tiles = (sbase + 1023u) & ~1023u;
    int tid = threadIdx.x, lane = tid & 31, wid = tid >> 5;
    int warp_m = wid & 1;
    int warp_n = wid >> 1;
    int m0 = blockIdx.y * TM;
    int n0 = blockIdx.x * TN;

    const __half* Ag = g_A + (size_t)m0 * KDIM;
    const __half* Wg = g_W + (size_t)n0 * KDIM;

    float c[4][8][4];
#pragma unroll
    for (int i = 0; i < 4; i++)
#pragma unroll
        for (int j = 0; j < 8; j++)
#pragma unroll
            for (int q = 0; q < 4; q++) c[i][j][q] = 0.0f;

    int a_row = (lane & 15);
    int a_colg = (lane >> 4) * 8;
    int b_row = (lane & 7) + ((lane >> 4) & 1) * 8;
    int b_colg = ((lane >> 3) & 1) * 8;

    uint32_t a_off_base = (uint32_t)((warp_m * 64 + a_row) * 128 + a_colg * 2);
    uint32_t b_off_base = (uint32_t)((warp_n * 64 + b_row) * 128 + b_colg * 2);

#pragma unroll
    for (int s = 0; s < STAGES - 1; s++) { load_stage(tiles, s, s, tid, Ag, Wg); CP_COMMIT(); }

    uint32_t abuf[2][4][4], bbuf[2][4][4];

    for (int t = 0; t < NKI; t++) {
        CP_WAIT2();
        __syncthreads();

        int nb = t + STAGES - 1;
        if (nb < NKI) load_stage(tiles, nb & 3, nb, tid, Ag, Wg);
        CP_COMMIT();

        uint32_t a_s = tiles + (t & 3) * STAGE_B;
        uint32_t w_s = a_s + A_TILE_B;

#pragma unroll
        for (int mt = 0; mt < 4; mt++)
            ldsm_x4(abuf[0][mt], a_s + sw128(a_off_base + (uint32_t)(mt * 16 * 128)));
#pragma unroll
        for (int nt2 = 0; nt2 < 4; nt2++)
            ldsm_x4(bbuf[0][nt2], w_s + sw128(b_off_base + (uint32_t)(nt2 * 16 * 128)));

#pragma unroll
        for (int kk = 0; kk < 4; kk++) {
            int cur = kk & 1, nxt = cur ^ 1;
            if (kk < 3) {
                uint32_t koff = (uint32_t)((kk + 1) * 16 * 2);
#pragma unroll
                for (int mt = 0; mt < 4; mt++)
                    ldsm_x4(abuf[nxt][mt],
                            a_s + sw128(a_off_base + (uint32_t)(mt * 16 * 128) + koff));
#pragma unroll
                for (int nt2 = 0; nt2 < 4; nt2++)
                    ldsm_x4(bbuf[nxt][nt2],
                            w_s + sw128(b_off_base + (uint32_t)(nt2 * 16 * 128) + koff));
            }
#pragma unroll
            for (int mt = 0; mt < 4; mt++)
#pragma unroll
                for (int nt2 = 0; nt2 < 4; nt2++) {
                    mma16816(c[mt][nt2 * 2],     abuf[cur][mt], bbuf[cur][nt2][0], bbuf[cur][nt2][1]);
                    mma16816(c[mt][nt2 * 2 + 1], abuf[cur][mt], bbuf[cur][nt2][2], bbuf[cur][nt2][3]);
                }
        }
    }

    int gr = lane >> 2, gc = (lane & 3) * 2;
#pragma unroll
    for (int mt = 0; mt < 4; mt++) {
#pragma unroll
        for (int nt = 0; nt < 8; nt++) {
            int row = m0 + warp_m * 64 + mt * 16 + gr;
            int col = n0 + warp_n * 64 + nt * 8 + gc;
            float2 v0, v1;
            v0.x = fminf(fmaxf(c[mt][nt][0] * INV_WSCALE, -1.0f), 1.0f);
            v0.y = fminf(fmaxf(c[mt][nt][1] * INV_WSCALE, -1.0f), 1.0f);
            v1.x = fminf(fmaxf(c[mt][nt][2] * INV_WSCALE, -1.0f), 1.0f);
            v1.y = fminf(fmaxf(c[mt][nt][3] * INV_WSCALE, -1.0f), 1.0f);
            *reinterpret_cast<float2*>(out + (size_t)row * OUTF + col) = v0;
            *reinterpret_cast<float2*>(out + (size_t)(row + 8) * OUTF + col) = v1;
        }
    }
}

// ---------------- launch ----------------
extern "C" void kernel_launch(void* const* d_in, const int* in_sizes, int n_in,
                              void* d_out, int out_size) {
    const float* x  = (const float*)d_in[0];   // [8192, 1024]
    const float* bw = (const float*)d_in[1];   // [1024, 1024]
    const float* sw = (const float*)d_in[2];   // [1024, 1024, 11]
    float* out = (float*)d_out;                // [8192, 1024]

    gen_AW_kernel<<<W_BLOCKS + A_BLOCKS, 256>>>(x, bw, sw);

    cudaFuncSetAttribute(kan_gemm_kernel,
                         cudaFuncAttributeMaxDynamicSharedMemorySize, SMEM_DYN);
    dim3 grid(OUTF / TN, BATCH / TM);          // (4, 64) = 256 CTAs
    kan_gemm_kernel<<<grid, NTHREADS, SMEM_DYN>>>(out);
}